// round 1
// baseline (speedup 1.0000x reference)
#include <cuda_runtime.h>

// ---------------------------------------------------------------------------
// Multi-slice ptychography forward model, fully fused.
//   V:        (8, 512, 512) f32
//   probe_re: (4, 128, 128) f32
//   probe_im: (4, 128, 128) f32
//   positions:(256, 2) int (int64 or int32 -- detected on device)
//   out amp:  (256, 128, 128) f32
//
// One CTA = one (mode, k). Wave lives in SMEM (SoA, pitch 129 floats).
// Per slice: rows pass = load*T -> DIF128 -> *Hx(bitrev)/128 -> DIT128 -> store
//            cols pass = load   -> DIF128 -> *Hy(bitrev)/128 -> DIT128 -> store
// Slice 7:   rows pass = load*T -> DIF128 -> store
//            cols pass = load   -> DIF128 -> |.|^2 into sRe
// Then bitrev-permute |psi|^2 to natural order, write to per-mode scratch.
// Finalize kernel: amp = sqrt(EPS + sum_m I_m / 16384).
// ---------------------------------------------------------------------------

#define PITCH 129
#define SMEM_FLOATS (2 * 128 * PITCH)

static __device__ float g_int[4u * 256u * 128u * 128u];   // 64 MB scratch

// ------------------------- warp-level 128-pt FFT ---------------------------
// Lane l holds v[j] = x[l + 32*j], j = 0..3 (positions in the length-128 line).
// twr/twi: per-lane forward twiddles W^e = exp(-2*pi*i*e/128) for
//   e = { l, l+32, 2l, (l&15)*4, (l&7)*8, (l&3)*16, (l&1)*32 }.

__device__ __forceinline__ void fft128_dif(float (&vr)[4], float (&vi)[4],
                                           const float (&twr)[7],
                                           const float (&twi)[7], int l)
{
    float ar, ai;
    // stage span 64: pairs (v0,v2) e=l ; (v1,v3) e=l+32
    ar = vr[0] - vr[2]; ai = vi[0] - vi[2];
    vr[0] += vr[2];     vi[0] += vi[2];
    vr[2] = ar * twr[0] - ai * twi[0];
    vi[2] = ar * twi[0] + ai * twr[0];
    ar = vr[1] - vr[3]; ai = vi[1] - vi[3];
    vr[1] += vr[3];     vi[1] += vi[3];
    vr[3] = ar * twr[1] - ai * twi[1];
    vi[3] = ar * twi[1] + ai * twr[1];
    // stage span 32: pairs (v0,v1), (v2,v3), e=2l
    ar = vr[0] - vr[1]; ai = vi[0] - vi[1];
    vr[0] += vr[1];     vi[0] += vi[1];
    vr[1] = ar * twr[2] - ai * twi[2];
    vi[1] = ar * twi[2] + ai * twr[2];
    ar = vr[2] - vr[3]; ai = vi[2] - vi[3];
    vr[2] += vr[3];     vi[2] += vi[3];
    vr[3] = ar * twr[2] - ai * twi[2];
    vi[3] = ar * twi[2] + ai * twr[2];
    // cross-lane spans 16, 8, 4, 2
#pragma unroll
    for (int st = 0; st < 4; st++) {
        const int s = 16 >> st;
        const bool hi = (l & s) != 0;
        const float sgn = hi ? -1.0f : 1.0f;
        const float tr = hi ? twr[3 + st] : 1.0f;
        const float ti = hi ? twi[3 + st] : 0.0f;
#pragma unroll
        for (int j = 0; j < 4; j++) {
            float pr = __shfl_xor_sync(0xffffffffu, vr[j], s);
            float pi = __shfl_xor_sync(0xffffffffu, vi[j], s);
            float xr = fmaf(sgn, vr[j], pr);
            float xi = fmaf(sgn, vi[j], pi);
            vr[j] = xr * tr - xi * ti;
            vi[j] = xr * ti + xi * tr;
        }
    }
    // cross-lane span 1 (no twiddle)
    {
        const bool hi = (l & 1) != 0;
        const float sgn = hi ? -1.0f : 1.0f;
#pragma unroll
        for (int j = 0; j < 4; j++) {
            float pr = __shfl_xor_sync(0xffffffffu, vr[j], 1);
            float pi = __shfl_xor_sync(0xffffffffu, vi[j], 1);
            vr[j] = fmaf(sgn, vr[j], pr);
            vi[j] = fmaf(sgn, vi[j], pi);
        }
    }
}

// Inverse (unnormalized) DIT, bit-reversed input -> natural output.
__device__ __forceinline__ void fft128_dit(float (&vr)[4], float (&vi)[4],
                                           const float (&twr)[7],
                                           const float (&twi)[7], int l)
{
    // span 1
    {
        const bool hi = (l & 1) != 0;
        const float sgn = hi ? -1.0f : 1.0f;
#pragma unroll
        for (int j = 0; j < 4; j++) {
            float pr = __shfl_xor_sync(0xffffffffu, vr[j], 1);
            float pi = __shfl_xor_sync(0xffffffffu, vi[j], 1);
            vr[j] = fmaf(sgn, vr[j], pr);
            vi[j] = fmaf(sgn, vi[j], pi);
        }
    }
    // spans 2, 4, 8, 16 : conj twiddles tw[6-st]
#pragma unroll
    for (int st = 0; st < 4; st++) {
        const int s = 2 << st;
        const bool hi = (l & s) != 0;
        const float sgn = hi ? -1.0f : 1.0f;
        const float tr = hi ? twr[6 - st] : 1.0f;
        const float ti = hi ? -twi[6 - st] : 0.0f;
#pragma unroll
        for (int j = 0; j < 4; j++) {
            float ur = vr[j] * tr - vi[j] * ti;
            float ui = vr[j] * ti + vi[j] * tr;
            float pr = __shfl_xor_sync(0xffffffffu, ur, s);
            float pi = __shfl_xor_sync(0xffffffffu, ui, s);
            vr[j] = fmaf(sgn, ur, pr);
            vi[j] = fmaf(sgn, ui, pi);
        }
    }
    // span 32 : conj tw2 on (v0,v1) and (v2,v3)
    {
        float ur = vr[1] * twr[2] + vi[1] * twi[2];
        float ui = vi[1] * twr[2] - vr[1] * twi[2];
        vr[1] = vr[0] - ur; vi[1] = vi[0] - ui;
        vr[0] += ur;        vi[0] += ui;
        ur = vr[3] * twr[2] + vi[3] * twi[2];
        ui = vi[3] * twr[2] - vr[3] * twi[2];
        vr[3] = vr[2] - ur; vi[3] = vi[2] - ui;
        vr[2] += ur;        vi[2] += ui;
    }
    // span 64 : conj tw0 on (v0,v2), conj tw1 on (v1,v3)
    {
        float ur = vr[2] * twr[0] + vi[2] * twi[0];
        float ui = vi[2] * twr[0] - vr[2] * twi[0];
        vr[2] = vr[0] - ur; vi[2] = vi[0] - ui;
        vr[0] += ur;        vi[0] += ui;
        ur = vr[3] * twr[1] + vi[3] * twi[1];
        ui = vi[3] * twr[1] - vr[3] * twi[1];
        vr[3] = vr[1] - ur; vi[3] = vi[1] - ui;
        vr[1] += ur;        vi[1] += ui;
    }
}

// ------------------------------- main kernel --------------------------------
__global__ void __launch_bounds__(512, 1)
msp_main(const float* __restrict__ V,
         const float* __restrict__ pre,
         const float* __restrict__ pim,
         const int*   __restrict__ ipos)
{
    extern __shared__ float smem[];
    float* sRe = smem;
    float* sIm = smem + 128 * PITCH;

    const int bid = blockIdx.x;
    const int k   = bid & 255;
    const int m   = bid >> 8;

    // positions may arrive as int64 or int32; detect (int64 -> high words 0)
    int py, px;
    {
        bool i64 = (ipos[1] | ipos[3] | ipos[5] | ipos[7] |
                    ipos[9] | ipos[11] | ipos[13] | ipos[15]) == 0;
        if (i64) { py = ipos[4 * k];  px = ipos[4 * k + 2]; }
        else     { py = ipos[2 * k];  px = ipos[2 * k + 1]; }
    }

    const int tid = threadIdx.x;
    const int l   = tid & 31;
    const int w   = tid >> 5;          // 16 warps

    // per-lane forward twiddles
    float twr[7], twi[7];
    {
        const int ev[7] = { l, l + 32, 2 * l, (l & 15) * 4, (l & 7) * 8,
                            (l & 3) * 16, (l & 1) * 32 };
#pragma unroll
        for (int i = 0; i < 7; i++) {
            float s, c;
            sincospif((float)ev[i] * (1.0f / 64.0f), &s, &c);
            twr[i] = c;
            twi[i] = -s;
        }
    }

    // per-lane Fresnel factors at bit-reversed stored positions, incl. 1/128
    float hbr[4], hbi[4];
#pragma unroll
    for (int j = 0; j < 4; j++) {
        int idx = l + 32 * j;
        int fb  = (int)(__brev((unsigned)idx) >> 25);
        float f = (float)(fb < 64 ? fb : fb - 128) * (1.0f / 25.6f);
        float ph = -0.25f * f * f;        // phase / pi  (lambda*dz = 0.25)
        float s, c;
        sincospif(ph, &s, &c);
        hbr[j] = c * (1.0f / 128.0f);
        hbi[j] = s * (1.0f / 128.0f);
    }

    const float* Vb = V + (py * 512 + px);
    const float* prm = pre + m * 16384;
    const float* pim_m = pim + m * 16384;

    for (int z = 0; z < 8; z++) {
        const float* Vz = Vb + z * (512 * 512);

        // ---------------- rows pass: transmit + DIF (+H+DIT if z<7) --------
        for (int rr = 0; rr < 8; rr++) {
            const int r = w + 16 * rr;
            float vr[4], vi[4];
#pragma unroll
            for (int j = 0; j < 4; j++) {
                const int c = l + 32 * j;
                float wr_, wi_;
                if (z == 0) {
                    wr_ = prm[r * 128 + c];
                    wi_ = pim_m[r * 128 + c];
                } else {
                    wr_ = sRe[r * PITCH + c];
                    wi_ = sIm[r * PITCH + c];
                }
                float v = Vz[r * 512 + c];
                float sv, cv;
                __sincosf(v, &sv, &cv);
                vr[j] = wr_ * cv - wi_ * sv;
                vi[j] = wr_ * sv + wi_ * cv;
            }
            fft128_dif(vr, vi, twr, twi, l);
            if (z < 7) {
#pragma unroll
                for (int j = 0; j < 4; j++) {
                    float ar = vr[j], ai = vi[j];
                    vr[j] = ar * hbr[j] - ai * hbi[j];
                    vi[j] = ar * hbi[j] + ai * hbr[j];
                }
                fft128_dit(vr, vi, twr, twi, l);
            }
#pragma unroll
            for (int j = 0; j < 4; j++) {
                sRe[r * PITCH + l + 32 * j] = vr[j];
                sIm[r * PITCH + l + 32 * j] = vi[j];
            }
        }
        __syncthreads();

        // ---------------- cols pass ----------------------------------------
        for (int cc = 0; cc < 8; cc++) {
            const int c = w + 16 * cc;
            float vr[4], vi[4];
#pragma unroll
            for (int j = 0; j < 4; j++) {
                const int r = l + 32 * j;
                vr[j] = sRe[r * PITCH + c];
                vi[j] = sIm[r * PITCH + c];
            }
            fft128_dif(vr, vi, twr, twi, l);
            if (z < 7) {
#pragma unroll
                for (int j = 0; j < 4; j++) {
                    float ar = vr[j], ai = vi[j];
                    vr[j] = ar * hbr[j] - ai * hbi[j];
                    vi[j] = ar * hbi[j] + ai * hbr[j];
                }
                fft128_dit(vr, vi, twr, twi, l);
#pragma unroll
                for (int j = 0; j < 4; j++) {
                    sRe[(l + 32 * j) * PITCH + c] = vr[j];
                    sIm[(l + 32 * j) * PITCH + c] = vi[j];
                }
            } else {
#pragma unroll
                for (int j = 0; j < 4; j++)
                    sRe[(l + 32 * j) * PITCH + c] =
                        vr[j] * vr[j] + vi[j] * vi[j];
            }
        }
        __syncthreads();
    }

    // bitrev permute |psi|^2 to natural order, coalesced store to scratch
    float* out = g_int + ((size_t)bid << 14);
    for (int i = tid; i < 16384; i += 512) {
        const int y = i >> 7, x = i & 127;
        const int ry = (int)(__brev((unsigned)y) >> 25);
        const int rx = (int)(__brev((unsigned)x) >> 25);
        out[i] = sRe[ry * PITCH + rx];
    }
}

// ------------------------------ finalize ------------------------------------
__global__ void msp_finalize(float* __restrict__ outp)
{
    const int i = blockIdx.x * blockDim.x + threadIdx.x;   // 4,194,304 total
    float s = g_int[i]
            + g_int[i + (1 << 22)]
            + g_int[i + (2 << 22)]
            + g_int[i + (3 << 22)];
    outp[i] = sqrtf(1e-10f + s * (1.0f / 16384.0f));
}

// ------------------------------ launcher ------------------------------------
extern "C" void kernel_launch(void* const* d_in, const int* in_sizes, int n_in,
                              void* d_out, int out_size)
{
    const float* V   = (const float*)d_in[0];
    const float* pre = (const float*)d_in[1];
    const float* pim = (const float*)d_in[2];
    const int*   pos = (const int*)d_in[3];
    float* out = (float*)d_out;
    (void)in_sizes; (void)n_in; (void)out_size;

    const size_t smem = SMEM_FLOATS * sizeof(float);   // 132096 B
    cudaFuncSetAttribute((const void*)msp_main,
                         cudaFuncAttributeMaxDynamicSharedMemorySize,
                         (int)smem);
    msp_main<<<1024, 512, smem>>>(V, pre, pim, pos);
    msp_finalize<<<16384, 256>>>(out);
}

// round 3
// speedup vs baseline: 1.1763x; 1.1763x over previous
#include <cuda_runtime.h>

// ---------------------------------------------------------------------------
// Multi-slice ptychography forward model, fully fused, f32x2-packed.
// One CTA = one (mode, k). Wave lives in SMEM (SoA, pitch 129 floats).
// Each warp processes TWO 128-pt FFT lines at once, packed into f32x2
// (Blackwell packed fp32: FADD2/FFMA2 via inline PTX). Twiddles, Fresnel
// factors and butterfly signs are identical across the pair -> packed
// broadcasts, no cross-half swaps. Exact fp32 RN arithmetic.
// ---------------------------------------------------------------------------

typedef unsigned long long u64;

#define PITCH 129
#define SMEM_FLOATS (2 * 128 * PITCH)

static __device__ float g_int[4u * 256u * 128u * 128u];   // 64 MB scratch

// ----------------------------- f32x2 helpers --------------------------------
__device__ __forceinline__ u64 pk(float a, float b) {
    u64 r; asm("mov.b64 %0,{%1,%2};" : "=l"(r) : "f"(a), "f"(b)); return r;
}
__device__ __forceinline__ void upk(u64 v, float& a, float& b) {
    asm("mov.b64 {%0,%1},%2;" : "=f"(a), "=f"(b) : "l"(v));
}
__device__ __forceinline__ u64 f2add(u64 a, u64 b) {
    u64 d; asm("add.rn.f32x2 %0,%1,%2;" : "=l"(d) : "l"(a), "l"(b)); return d;
}
__device__ __forceinline__ u64 f2sub(u64 a, u64 b) {
    u64 d; asm("sub.rn.f32x2 %0,%1,%2;" : "=l"(d) : "l"(a), "l"(b)); return d;
}
__device__ __forceinline__ u64 f2mul(u64 a, u64 b) {
    u64 d; asm("mul.rn.f32x2 %0,%1,%2;" : "=l"(d) : "l"(a), "l"(b)); return d;
}
__device__ __forceinline__ u64 f2fma(u64 a, u64 b, u64 c) {
    u64 d; asm("fma.rn.f32x2 %0,%1,%2,%3;" : "=l"(d) : "l"(a), "l"(b), "l"(c)); return d;
}
__device__ __forceinline__ u64 shx(u64 v, int s) {
    float a, b; upk(v, a, b);
    a = __shfl_xor_sync(0xffffffffu, a, s);
    b = __shfl_xor_sync(0xffffffffu, b, s);
    return pk(a, b);
}

// ------------------------- packed twiddle context ---------------------------
// Lane l holds line positions l + 32j, j = 0..3.
// Register stages: span 64 (e=l for pair(0,2), e=l+32 for pair(1,3)),
//                  span 32 (e=2l). Cross-lane: spans 16,8,4,2 with effective
// twiddles (hi-lane only, lo lanes get (1,0)), then span 1 (sign only).
struct Tw {
    u64 t0r, t0i, t1r, t1i, t2r, t2i;    // register-stage twiddles
    u64 ctr[4], cti[4], ncti[4];          // effective cross-stage twiddles
    u64 sg[5];                            // butterfly signs, spans 16,8,4,2,1
};

__device__ __forceinline__ void dif(u64 (&R)[4], u64 (&I)[4], const Tw& T)
{
    // span 64
    {
        u64 dr = f2sub(R[0], R[2]), di = f2sub(I[0], I[2]);
        R[0] = f2add(R[0], R[2]);  I[0] = f2add(I[0], I[2]);
        R[2] = f2sub(f2mul(dr, T.t0r), f2mul(di, T.t0i));
        I[2] = f2fma(dr, T.t0i, f2mul(di, T.t0r));
        dr = f2sub(R[1], R[3]);  di = f2sub(I[1], I[3]);
        R[1] = f2add(R[1], R[3]);  I[1] = f2add(I[1], I[3]);
        R[3] = f2sub(f2mul(dr, T.t1r), f2mul(di, T.t1i));
        I[3] = f2fma(dr, T.t1i, f2mul(di, T.t1r));
    }
    // span 32
    {
        u64 dr = f2sub(R[0], R[1]), di = f2sub(I[0], I[1]);
        R[0] = f2add(R[0], R[1]);  I[0] = f2add(I[0], I[1]);
        R[1] = f2sub(f2mul(dr, T.t2r), f2mul(di, T.t2i));
        I[1] = f2fma(dr, T.t2i, f2mul(di, T.t2r));
        dr = f2sub(R[2], R[3]);  di = f2sub(I[2], I[3]);
        R[2] = f2add(R[2], R[3]);  I[2] = f2add(I[2], I[3]);
        R[3] = f2sub(f2mul(dr, T.t2r), f2mul(di, T.t2i));
        I[3] = f2fma(dr, T.t2i, f2mul(di, T.t2r));
    }
    // cross-lane spans 16,8,4,2
#pragma unroll
    for (int ct = 0; ct < 4; ct++) {
        const int s = 16 >> ct;
#pragma unroll
        for (int j = 0; j < 4; j++) {
            u64 pR = shx(R[j], s), pI = shx(I[j], s);
            u64 xR = f2fma(T.sg[ct], R[j], pR);
            u64 xI = f2fma(T.sg[ct], I[j], pI);
            R[j] = f2fma(xI, T.ncti[ct], f2mul(xR, T.ctr[ct]));
            I[j] = f2fma(xI, T.ctr[ct],  f2mul(xR, T.cti[ct]));
        }
    }
    // span 1 (no twiddle)
#pragma unroll
    for (int j = 0; j < 4; j++) {
        u64 pR = shx(R[j], 1), pI = shx(I[j], 1);
        R[j] = f2fma(T.sg[4], R[j], pR);
        I[j] = f2fma(T.sg[4], I[j], pI);
    }
}

// Inverse (unnormalized) DIT, bit-reversed input -> natural output.
__device__ __forceinline__ void dit(u64 (&R)[4], u64 (&I)[4], const Tw& T)
{
    // span 1
#pragma unroll
    for (int j = 0; j < 4; j++) {
        u64 pR = shx(R[j], 1), pI = shx(I[j], 1);
        R[j] = f2fma(T.sg[4], R[j], pR);
        I[j] = f2fma(T.sg[4], I[j], pI);
    }
    // spans 2,4,8,16 : conj of the DIF effective twiddles (same span)
#pragma unroll
    for (int kk = 0; kk < 4; kk++) {
        const int s = 2 << kk;
        const int ct = 3 - kk;
#pragma unroll
        for (int j = 0; j < 4; j++) {
            u64 uR = f2fma(I[j], T.cti[ct],  f2mul(R[j], T.ctr[ct]));
            u64 uI = f2fma(R[j], T.ncti[ct], f2mul(I[j], T.ctr[ct]));
            u64 pR = shx(uR, s), pI = shx(uI, s);
            R[j] = f2fma(T.sg[ct], uR, pR);
            I[j] = f2fma(T.sg[ct], uI, pI);
        }
    }
    // span 32 : conj t2 on (0,1) and (2,3)
    {
        u64 ur = f2fma(I[1], T.t2i, f2mul(R[1], T.t2r));
        u64 ui = f2sub(f2mul(I[1], T.t2r), f2mul(R[1], T.t2i));
        R[1] = f2sub(R[0], ur);  I[1] = f2sub(I[0], ui);
        R[0] = f2add(R[0], ur);  I[0] = f2add(I[0], ui);
        ur = f2fma(I[3], T.t2i, f2mul(R[3], T.t2r));
        ui = f2sub(f2mul(I[3], T.t2r), f2mul(R[3], T.t2i));
        R[3] = f2sub(R[2], ur);  I[3] = f2sub(I[2], ui);
        R[2] = f2add(R[2], ur);  I[2] = f2add(I[2], ui);
    }
    // span 64 : conj t0 on (0,2), conj t1 on (1,3)
    {
        u64 ur = f2fma(I[2], T.t0i, f2mul(R[2], T.t0r));
        u64 ui = f2sub(f2mul(I[2], T.t0r), f2mul(R[2], T.t0i));
        R[2] = f2sub(R[0], ur);  I[2] = f2sub(I[0], ui);
        R[0] = f2add(R[0], ur);  I[0] = f2add(I[0], ui);
        ur = f2fma(I[3], T.t1i, f2mul(R[3], T.t1r));
        ui = f2sub(f2mul(I[3], T.t1r), f2mul(R[3], T.t1i));
        R[3] = f2sub(R[1], ur);  I[3] = f2sub(I[1], ui);
        R[1] = f2add(R[1], ur);  I[1] = f2add(I[1], ui);
    }
}

// ------------------------------- main kernel --------------------------------
__global__ void __launch_bounds__(512, 1)
msp_main(const float* __restrict__ V,
         const float* __restrict__ pre,
         const float* __restrict__ pim,
         const int*   __restrict__ ipos)
{
    extern __shared__ float smem[];
    float* sRe = smem;
    float* sIm = smem + 128 * PITCH;

    const int bid = blockIdx.x;
    const int k   = bid & 255;
    const int m   = bid >> 8;

    int py, px;
    {
        bool i64 = (ipos[1] | ipos[3] | ipos[5] | ipos[7] |
                    ipos[9] | ipos[11] | ipos[13] | ipos[15]) == 0;
        if (i64) { py = ipos[4 * k];  px = ipos[4 * k + 2]; }
        else     { py = ipos[2 * k];  px = ipos[2 * k + 1]; }
    }

    const int tid = threadIdx.x;
    const int l   = tid & 31;
    const int w   = tid >> 5;          // 16 warps

    Tw T;
    {
        float s, c;
        sincospif((float)l        * (1.0f / 64.0f), &s, &c);
        T.t0r = pk(c, c);  T.t0i = pk(-s, -s);
        sincospif((float)(l + 32) * (1.0f / 64.0f), &s, &c);
        T.t1r = pk(c, c);  T.t1i = pk(-s, -s);
        sincospif((float)(2 * l)  * (1.0f / 64.0f), &s, &c);
        T.t2r = pk(c, c);  T.t2i = pk(-s, -s);
    }
    {
        const int ev[4]  = { (l & 15) * 4, (l & 7) * 8, (l & 3) * 16, (l & 1) * 32 };
        const int hib[4] = { l & 16, l & 8, l & 4, l & 2 };
#pragma unroll
        for (int ct = 0; ct < 4; ct++) {
            float s, c;
            sincospif((float)ev[ct] * (1.0f / 64.0f), &s, &c);
            float tr = hib[ct] ? c : 1.0f;
            float ti = hib[ct] ? -s : 0.0f;
            T.ctr[ct]  = pk(tr, tr);
            T.cti[ct]  = pk(ti, ti);
            T.ncti[ct] = pk(-ti, -ti);
        }
        const int sp[5] = { 16, 8, 4, 2, 1 };
#pragma unroll
        for (int i = 0; i < 5; i++) {
            float g = (l & sp[i]) ? -1.0f : 1.0f;
            T.sg[i] = pk(g, g);
        }
    }

    // Fresnel factors at bit-reversed stored positions, 1/128 folded in
    u64 Hr[4], Hi[4];
#pragma unroll
    for (int j = 0; j < 4; j++) {
        int idx = l + 32 * j;
        int fb  = (int)(__brev((unsigned)idx) >> 25);
        float f = (float)(fb < 64 ? fb : fb - 128) * (1.0f / 25.6f);
        float s, c;
        sincospif(-0.25f * f * f, &s, &c);      // lambda*dz = 0.25
        Hr[j] = pk(c * (1.0f / 128.0f), c * (1.0f / 128.0f));
        Hi[j] = pk(s * (1.0f / 128.0f), s * (1.0f / 128.0f));
    }

    const float* Vb   = V + (py * 512 + px);
    const float* prm  = pre + m * 16384;
    const float* pimm = pim + m * 16384;

    for (int z = 0; z < 8; z++) {
        const float* Vz = Vb + z * (512 * 512);

        // ---------------- rows pass: transmit + DIF (+H+DIT if z<7) --------
        for (int p = 0; p < 4; p++) {
            const int rA = 2 * (w + 16 * p), rB = rA + 1;
            u64 R[4], I[4];
#pragma unroll
            for (int j = 0; j < 4; j++) {
                const int c = l + 32 * j;
                float wra, wrb, wia, wib;
                if (z == 0) {
                    wra = prm[rA * 128 + c];  wrb = prm[rB * 128 + c];
                    wia = pimm[rA * 128 + c]; wib = pimm[rB * 128 + c];
                } else {
                    wra = sRe[rA * PITCH + c];  wrb = sRe[rB * PITCH + c];
                    wia = sIm[rA * PITCH + c];  wib = sIm[rB * PITCH + c];
                }
                float va = Vz[rA * 512 + c], vb = Vz[rB * 512 + c];
                float sa, ca, sb, cb;
                __sincosf(va, &sa, &ca);
                __sincosf(vb, &sb, &cb);
                u64 wr = pk(wra, wrb), wi = pk(wia, wib);
                u64 cp = pk(ca, cb),  spn = pk(sa, sb);
                R[j] = f2sub(f2mul(wr, cp), f2mul(wi, spn));
                I[j] = f2fma(wr, spn, f2mul(wi, cp));
            }
            dif(R, I, T);
            if (z < 7) {
#pragma unroll
                for (int j = 0; j < 4; j++) {
                    u64 rr = f2sub(f2mul(R[j], Hr[j]), f2mul(I[j], Hi[j]));
                    I[j]   = f2fma(R[j], Hi[j], f2mul(I[j], Hr[j]));
                    R[j]   = rr;
                }
                dit(R, I, T);
            }
#pragma unroll
            for (int j = 0; j < 4; j++) {
                const int c = l + 32 * j;
                float a, b;
                upk(R[j], a, b);  sRe[rA * PITCH + c] = a;  sRe[rB * PITCH + c] = b;
                upk(I[j], a, b);  sIm[rA * PITCH + c] = a;  sIm[rB * PITCH + c] = b;
            }
        }
        __syncthreads();

        // ---------------- cols pass ----------------------------------------
        for (int p = 0; p < 4; p++) {
            const int cA = 2 * (w + 16 * p), cB = cA + 1;
            u64 R[4], I[4];
#pragma unroll
            for (int j = 0; j < 4; j++) {
                const int r = l + 32 * j;
                R[j] = pk(sRe[r * PITCH + cA], sRe[r * PITCH + cB]);
                I[j] = pk(sIm[r * PITCH + cA], sIm[r * PITCH + cB]);
            }
            dif(R, I, T);
            if (z < 7) {
#pragma unroll
                for (int j = 0; j < 4; j++) {
                    u64 rr = f2sub(f2mul(R[j], Hr[j]), f2mul(I[j], Hi[j]));
                    I[j]   = f2fma(R[j], Hi[j], f2mul(I[j], Hr[j]));
                    R[j]   = rr;
                }
                dit(R, I, T);
#pragma unroll
                for (int j = 0; j < 4; j++) {
                    const int r = l + 32 * j;
                    float a, b;
                    upk(R[j], a, b);  sRe[r * PITCH + cA] = a;  sRe[r * PITCH + cB] = b;
                    upk(I[j], a, b);  sIm[r * PITCH + cA] = a;  sIm[r * PITCH + cB] = b;
                }
            } else {
#pragma unroll
                for (int j = 0; j < 4; j++) {
                    const int r = l + 32 * j;
                    u64 mg = f2fma(R[j], R[j], f2mul(I[j], I[j]));
                    float a, b;
                    upk(mg, a, b);
                    sRe[r * PITCH + cA] = a;
                    sRe[r * PITCH + cB] = b;
                }
            }
        }
        __syncthreads();
    }

    // bitrev permute |psi|^2 to natural order, coalesced store to scratch
    float* out = g_int + ((size_t)bid << 14);
    for (int i = tid; i < 16384; i += 512) {
        const int y = i >> 7, x = i & 127;
        const int ry = (int)(__brev((unsigned)y) >> 25);
        const int rx = (int)(__brev((unsigned)x) >> 25);
        out[i] = sRe[ry * PITCH + rx];
    }
}

// ------------------------------ finalize ------------------------------------
__global__ void msp_finalize(float* __restrict__ outp)
{
    const size_t i = ((size_t)blockIdx.x * blockDim.x + threadIdx.x) * 4;
    float4 a = *(const float4*)(g_int + i);
    float4 b = *(const float4*)(g_int + i + ((size_t)1 << 22));
    float4 c = *(const float4*)(g_int + i + ((size_t)2 << 22));
    float4 d = *(const float4*)(g_int + i + ((size_t)3 << 22));
    float4 o;
    o.x = sqrtf(1e-10f + (a.x + b.x + c.x + d.x) * (1.0f / 16384.0f));
    o.y = sqrtf(1e-10f + (a.y + b.y + c.y + d.y) * (1.0f / 16384.0f));
    o.z = sqrtf(1e-10f + (a.z + b.z + c.z + d.z) * (1.0f / 16384.0f));
    o.w = sqrtf(1e-10f + (a.w + b.w + c.w + d.w) * (1.0f / 16384.0f));
    *(float4*)(outp + i) = o;
}

// ------------------------------ launcher ------------------------------------
extern "C" void kernel_launch(void* const* d_in, const int* in_sizes, int n_in,
                              void* d_out, int out_size)
{
    const float* V   = (const float*)d_in[0];
    const float* pre = (const float*)d_in[1];
    const float* pim = (const float*)d_in[2];
    const int*   pos = (const int*)d_in[3];
    float* out = (float*)d_out;
    (void)in_sizes; (void)n_in; (void)out_size;

    const size_t smem = SMEM_FLOATS * sizeof(float);   // 132096 B
    cudaFuncSetAttribute((const void*)msp_main,
                         cudaFuncAttributeMaxDynamicSharedMemorySize,
                         (int)smem);
    msp_main<<<1024, 512, smem>>>(V, pre, pim, pos);
    msp_finalize<<<4096, 256>>>(out);
}